// round 14
// baseline (speedup 1.0000x reference)
#include <cuda_runtime.h>
#include <cuda_fp16.h>
#include <cstdint>
#include <math.h>

// Problem constants (fixed by the dataset)
#define BB 8
#define HH 64
#define WW 64
#define CC 256
#define FF 256
#define NPIX (BB*HH*WW)   // 32768
#define KTOT 2304         // 9*256

__device__ float g_om[NPIX * 27];
__device__ __half g_Wh[FF * KTOT];     // main weights transposed: Wh[f][k]
__device__ __half g_OMWh[32 * KTOT];   // om weights: OMWh[f][tap*256+c], f 27..31 = 0

// ============================ helpers ============================
__device__ __forceinline__ uint32_t smem_u32(const void* p) {
    uint32_t a;
    asm("{ .reg .u64 t; cvta.to.shared.u64 t, %1; cvt.u32.u64 %0, t; }"
        : "=r"(a) : "l"(p));
    return a;
}
#define CP_ASYNC16(dst, src) \
    asm volatile("cp.async.cg.shared.global [%0], [%1], 16;" :: "r"(dst), "l"(src) : "memory")
#define CP_COMMIT() asm volatile("cp.async.commit_group;" ::: "memory")
#define CP_WAIT0()  asm volatile("cp.async.wait_group 0;" ::: "memory")

#define LDSM4(r, a) \
    asm volatile("ldmatrix.sync.aligned.m8n8.x4.shared.b16 {%0,%1,%2,%3}, [%4];" \
        : "=r"((r)[0]), "=r"((r)[1]), "=r"((r)[2]), "=r"((r)[3]) : "r"(a))

__device__ __forceinline__ void mma_f16(float* c, const uint32_t* a, const uint32_t* b) {
    asm volatile("mma.sync.aligned.m16n8k16.row.col.f32.f16.f16.f32 "
        "{%0,%1,%2,%3}, {%4,%5,%6,%7}, {%8,%9}, {%0,%1,%2,%3};"
        : "+f"(c[0]), "+f"(c[1]), "+f"(c[2]), "+f"(c[3])
        : "r"(a[0]), "r"(a[1]), "r"(a[2]), "r"(a[3]), "r"(b[0]), "r"(b[1]));
}

// ============================ Kernel 0a: main W transpose + fp16 ==============
__global__ __launch_bounds__(256) void transpose_w(const float* __restrict__ W) {
    __shared__ float t[32][33];
    int k0 = blockIdx.x * 32, f0 = blockIdx.y * 32;
    int tx = threadIdx.x & 31, ty = threadIdx.x >> 5;
    #pragma unroll
    for (int r = 0; r < 32; r += 8)
        t[ty + r][tx] = W[(k0 + ty + r) * 256 + f0 + tx];
    __syncthreads();
    #pragma unroll
    for (int r = 0; r < 32; r += 8)
        g_Wh[(f0 + ty + r) * KTOT + k0 + tx] = __float2half_rn(t[tx][ty + r]);
}

// ============================ Kernel 0b: om W prep (27->32 pad, fp16) =========
__global__ __launch_bounds__(256) void om_prep_w(const float* __restrict__ omw) {
    int k = blockIdx.x * 256 + threadIdx.x;   // 0..2303
    if (k < KTOT) {
        #pragma unroll
        for (int f = 0; f < 32; ++f) {
            float v = (f < 27) ? omw[k * 27 + f] : 0.f;
            g_OMWh[f * KTOT + k] = __float2half_rn(v);
        }
    }
}

// ============================ Kernel 1: om conv via fp16 mma ==================
__global__ __launch_bounds__(256, 1) void om_mma_kernel(
    const float* __restrict__ x,      // [8,64,64,256]
    const float* __restrict__ omb)    // [27]
{
    __shared__ __align__(16) char smem[2 * 8192 + 2 * 2048];   // A 16KB + B 4KB
    const uint32_t sb = smem_u32(smem);
    const uint32_t A_OFF = 0, B_OFF = 16384;
    const int tid = threadIdx.x;
    const int lane = tid & 31, wid = tid >> 5;
    const int m0 = blockIdx.x * 128;

    float acc[4][4];
    #pragma unroll
    for (int nt = 0; nt < 4; ++nt)
        #pragma unroll
        for (int q = 0; q < 4; ++q) acc[nt][q] = 0.f;

    const int rA = wid * 16 + (lane & 7) + ((lane >> 3) & 1) * 8;
    const int kbitA = lane >> 4;
    const int rB = (lane & 7) + (lane >> 4) * 8;
    const int kbitB = (lane >> 3) & 1;
    uint32_t koffA[2], koffB[2];
    #pragma unroll
    for (int ks = 0; ks < 2; ++ks) {
        koffA[ks] = (uint32_t)(((ks * 2 + kbitA) ^ ((rA >> 1) & 3)) * 16);
        koffB[ks] = (uint32_t)(((ks * 2 + kbitB) ^ ((rB >> 1) & 3)) * 16);
    }
    const uint32_t rowAoff = (uint32_t)(rA * 64);
    const uint32_t rowBoff = (uint32_t)(rB * 64);

    const int px = tid >> 1, half = tid & 1;
    const int m = m0 + px;
    const int y = (m >> 6) & 63, xc = m & 63, b = m >> 12;

    auto stageA = [&](int j, int stage) {
        const int tap = j >> 3;
        const int ky = tap / 3, kx = tap - ky * 3;
        const int sy = y - 1 + ky, sx = xc - 1 + kx;
        const bool valid = ((unsigned)sy < 64u) && ((unsigned)sx < 64u);
        float4 va = {0,0,0,0}, vb = {0,0,0,0}, vc = {0,0,0,0}, vd = {0,0,0,0};
        if (valid) {
            const float* src = x + (((b << 12) + sy * 64 + sx) << 8)
                               + (j & 7) * 32 + half * 16;
            va = *(const float4*)(src);
            vb = *(const float4*)(src + 4);
            vc = *(const float4*)(src + 8);
            vd = *(const float4*)(src + 12);
        }
        __half2 h0 = __floats2half2_rn(va.x, va.y);
        __half2 h1 = __floats2half2_rn(va.z, va.w);
        __half2 h2 = __floats2half2_rn(vb.x, vb.y);
        __half2 h3 = __floats2half2_rn(vb.z, vb.w);
        __half2 h4 = __floats2half2_rn(vc.x, vc.y);
        __half2 h5 = __floats2half2_rn(vc.z, vc.w);
        __half2 h6 = __floats2half2_rn(vd.x, vd.y);
        __half2 h7 = __floats2half2_rn(vd.z, vd.w);
        uint4 s0, s1;
        s0.x = *(uint32_t*)&h0; s0.y = *(uint32_t*)&h1;
        s0.z = *(uint32_t*)&h2; s0.w = *(uint32_t*)&h3;
        s1.x = *(uint32_t*)&h4; s1.y = *(uint32_t*)&h5;
        s1.z = *(uint32_t*)&h6; s1.w = *(uint32_t*)&h7;
        const int g0 = half * 2, ss = (px >> 1) & 3;
        char* base = smem + A_OFF + stage * 8192 + px * 64;
        *(uint4*)(base + ((g0 ^ ss) * 16)) = s0;
        *(uint4*)(base + (((g0 + 1) ^ ss) * 16)) = s1;
    };
    auto stageB = [&](int j, int stage) {
        if (tid < 128) {
            const int n = tid >> 2, g = tid & 3;
            const uint32_t dst = sb + B_OFF + stage * 2048 + n * 64
                                 + ((g ^ ((n >> 1) & 3)) * 16);
            CP_ASYNC16(dst, g_OMWh + (size_t)n * KTOT + j * 32 + g * 8);
        }
    };

    stageB(0, 0);
    CP_COMMIT();
    stageA(0, 0);
    CP_WAIT0();
    __syncthreads();

    for (int j = 0; j < 72; ++j) {
        const int s = j & 1, ns = s ^ 1;
        if (j < 71) {
            stageB(j + 1, ns);
            CP_COMMIT();
            stageA(j + 1, ns);
        }
        const uint32_t Ab = sb + A_OFF + s * 8192 + rowAoff;
        const uint32_t Bb = sb + B_OFF + s * 2048 + rowBoff;
        #pragma unroll
        for (int ks = 0; ks < 2; ++ks) {
            uint32_t a[4];
            LDSM4(a, Ab + koffA[ks]);
            uint32_t b0[4], b1[4];
            LDSM4(b0, Bb + 0 * 1024 + koffB[ks]);
            LDSM4(b1, Bb + 1 * 1024 + koffB[ks]);
            mma_f16(acc[0], a, b0);
            mma_f16(acc[1], a, b0 + 2);
            mma_f16(acc[2], a, b1);
            mma_f16(acc[3], a, b1 + 2);
        }
        if (j < 71) CP_WAIT0();
        __syncthreads();
    }

    const int g = lane >> 2, cq = lane & 3;
    #pragma unroll
    for (int nt = 0; nt < 4; ++nt) {
        #pragma unroll
        for (int q = 0; q < 4; ++q) {
            const int f = nt * 8 + 2 * cq + (q & 1);
            if (f < 27) {
                const int row = m0 + wid * 16 + g + ((q >> 1) * 8);
                float v = acc[nt][q] + omb[f];
                if (f >= 18) v = 2.f / (1.f + expf(-v));
                g_om[row * 27 + f] = v;
            }
        }
    }
}

// ============================ Kernel 2: fused sampling + fp16 mma GEMM ========
// CTA: 512 threads (16 warps), tile M=128 x N=256. Grid 256 m-tiles.
// Warps: 4(m) x 4(n), warp tile 32x64, fp16 m16n8k16, acc[2 mt][8 nt][4] f32.
// 36 K-chunks of 64 fp16 (9 kernel pts x 4 segs); 2 smem stages; gathers for
// chunk j+1 pipelined through the 4 MMA ks-blocks of chunk j.
// A rows: 128 x 128B fp16; B rows: 256 x 128B. Swizzle granule g^(row&7).
#define SM_SW 0              // [2][128] float4 bilinear weights (4KB)
#define SM_SO 4096           // [2][128] int4 corner offsets (4KB)
#define SM_A  8192           // [2][128][128B] fp16 (32KB)
#define SM_B  40960          // [2][256][128B] fp16 (64KB)
#define SM_TOTAL 106496

__device__ __forceinline__ void compute_params3(int kp, int m, float4* sw4, int4* so4) {
    const float* omp = g_om + m * 27;
    const int y = (m >> 6) & 63, xc = m & 63, b = m >> 12;
    const int ky = kp / 3, kx = kp - ky * 3;
    float py = (float)(y - 1 + ky) + omp[2 * kp];
    float px = (float)(xc - 1 + kx) + omp[2 * kp + 1];
    float msk = omp[18 + kp];
    float y0f = floorf(py), x0f = floorf(px);
    float wy1 = py - y0f, wy0 = 1.f - wy1;
    float wx1 = px - x0f, wx0 = 1.f - wx1;
    int iy0 = (int)y0f, ix0 = (int)x0f;
    int iy1 = iy0 + 1, ix1 = ix0 + 1;
    bool vy0 = (unsigned)iy0 < 64u, vy1 = (unsigned)iy1 < 64u;
    bool vx0 = (unsigned)ix0 < 64u, vx1 = (unsigned)ix1 < 64u;
    int cy0 = min(max(iy0, 0), 63), cy1 = min(max(iy1, 0), 63);
    int cx0 = min(max(ix0, 0), 63), cx1 = min(max(ix1, 0), 63);
    int base = b << 12;
    int4 o;
    o.x = (base + cy0 * 64 + cx0) << 8;
    o.y = (base + cy0 * 64 + cx1) << 8;
    o.z = (base + cy1 * 64 + cx0) << 8;
    o.w = (base + cy1 * 64 + cx1) << 8;
    float4 w;
    w.x = (vy0 && vx0) ? wy0 * wx0 * msk : 0.f;
    w.y = (vy0 && vx1) ? wy0 * wx1 * msk : 0.f;
    w.z = (vy1 && vx0) ? wy1 * wx0 * msk : 0.f;
    w.w = (vy1 && vx1) ? wy1 * wx1 * msk : 0.f;
    *so4 = o;
    *sw4 = w;
}

// Stage B chunk j (256 rows x 128B): 512 threads, 4 granules each.
__device__ __forceinline__ void loadB3(uint32_t sb, int j, int stage, int tid) {
    const int n = tid >> 1, g0 = (tid & 1) * 4;
    const int ss = n & 7;
    const uint32_t dbase = sb + SM_B + stage * 32768 + n * 128;
    const __half* src = g_Wh + (size_t)n * KTOT + j * 64;
    #pragma unroll
    for (int g = g0; g < g0 + 4; ++g)
        CP_ASYNC16(dbase + ((g ^ ss) * 16), src + g * 8);
}

__global__ __launch_bounds__(512, 1) void dcn_mma_kernel(
    const float* __restrict__ x,      // [8,64,64,256]
    const float* __restrict__ bias,   // [256]
    float* __restrict__ out)          // [32768,256]
{
    extern __shared__ char smem[];
    const uint32_t sb = smem_u32(smem);
    const int tid = threadIdx.x;
    const int lane = tid & 31, wid = tid >> 5;
    const int wm = wid & 3, wn = wid >> 2;     // 4m x 4n
    const int m0 = blockIdx.x * 128;

    float4* SW0 = (float4*)(smem + SM_SW);
    int4*   SO0 = (int4*)(smem + SM_SO);

    float acc[2][8][4];
    #pragma unroll
    for (int mt = 0; mt < 2; ++mt)
        #pragma unroll
        for (int nt = 0; nt < 8; ++nt)
            #pragma unroll
            for (int q = 0; q < 4; ++q) acc[mt][nt][q] = 0.f;

    // ldmatrix addressing (128B rows, granule ^ (row&7))
    const int rA = wm * 32 + (lane & 7) + ((lane >> 3) & 1) * 8;
    const int kbitA = lane >> 4;
    const int rB = wn * 64 + (lane & 7) + (lane >> 4) * 8;
    const int kbitB = (lane >> 3) & 1;
    uint32_t koffA[4], koffB[4];
    #pragma unroll
    for (int ks = 0; ks < 4; ++ks) {
        koffA[ks] = (uint32_t)(((ks * 2 + kbitA) ^ (rA & 7)) * 16);
        koffB[ks] = (uint32_t)(((ks * 2 + kbitB) ^ (rB & 7)) * 16);
    }
    const uint32_t rowAoff = (uint32_t)(rA * 128);
    const uint32_t rowBoff = (uint32_t)(rB * 128);

    // sampling identity: 4 threads per pixel, thread owns 16 channels (2 halves)
    const int spx = tid >> 2, sq = tid & 3;
    const int pxs = spx & 7;
    const uint32_t stsoff0 = (uint32_t)(spx * 128 + (((sq * 2 + 0) ^ pxs) * 16));
    const uint32_t stsoff1 = (uint32_t)(spx * 128 + (((sq * 2 + 1) ^ pxs) * 16));

    // ---------------- Prologue ----------------
    if (tid < 128) compute_params3(0, m0 + tid, SW0 + tid, SO0 + tid);
    __syncthreads();
    loadB3(sb, 0, 0, tid);
    CP_COMMIT();
    {
        const int4 o = SO0[spx];
        const float4 w = SW0[spx];
        #pragma unroll
        for (int h = 0; h < 2; ++h) {
            const int cb = sq * 16 + h * 8;
            float4 v0a = *(const float4*)(x + o.x + cb), v0b = *(const float4*)(x + o.x + cb + 4);
            float4 v1a = *(const float4*)(x + o.y + cb), v1b = *(const float4*)(x + o.y + cb + 4);
            float4 v2a = *(const float4*)(x + o.z + cb), v2b = *(const float4*)(x + o.z + cb + 4);
            float4 v3a = *(const float4*)(x + o.w + cb), v3b = *(const float4*)(x + o.w + cb + 4);
            float c[8];
            c[0] = w.x*v0a.x + w.y*v1a.x + w.z*v2a.x + w.w*v3a.x;
            c[1] = w.x*v0a.y + w.y*v1a.y + w.z*v2a.y + w.w*v3a.y;
            c[2] = w.x*v0a.z + w.y*v1a.z + w.z*v2a.z + w.w*v3a.z;
            c[3] = w.x*v0a.w + w.y*v1a.w + w.z*v2a.w + w.w*v3a.w;
            c[4] = w.x*v0b.x + w.y*v1b.x + w.z*v2b.x + w.w*v3b.x;
            c[5] = w.x*v0b.y + w.y*v1b.y + w.z*v2b.y + w.w*v3b.y;
            c[6] = w.x*v0b.z + w.y*v1b.z + w.z*v2b.z + w.w*v3b.z;
            c[7] = w.x*v0b.w + w.y*v1b.w + w.z*v2b.w + w.w*v3b.w;
            __half2 h0 = __floats2half2_rn(c[0], c[1]);
            __half2 h1 = __floats2half2_rn(c[2], c[3]);
            __half2 h2 = __floats2half2_rn(c[4], c[5]);
            __half2 h3 = __floats2half2_rn(c[6], c[7]);
            uint4 st;
            st.x = *(uint32_t*)&h0; st.y = *(uint32_t*)&h1;
            st.z = *(uint32_t*)&h2; st.w = *(uint32_t*)&h3;
            *(uint4*)(smem + SM_A + (h ? stsoff1 : stsoff0)) = st;
        }
    }
    CP_WAIT0();
    __syncthreads();

    // ---------------- Main loop: consume chunk j (64 K), produce j+1 ----------
    for (int j = 0; j < 35; ++j) {
        const int s = j & 1, ns = s ^ 1;
        const int pb1 = ((j + 1) >> 2) & 1;
        const float4* SWn = SW0 + pb1 * 128;
        const int4*   SOn = SO0 + pb1 * 128;
        const uint32_t Ans = (uint32_t)(SM_A + ns * 16384);

        loadB3(sb, j + 1, ns, tid);
        CP_COMMIT();

        const uint32_t Ab = sb + SM_A + s * 16384 + rowAoff;
        const uint32_t Bb = sb + SM_B + s * 32768 + rowBoff;

        const int4 o = SOn[spx];
        const float4 w = SWn[spx];
        const int cbh0 = ((j + 1) & 3) * 64 + sq * 16;

        float c[8];
        float4 va, vb, vc, vd;

        // --- gather half0 corners 0,1 ---
        va = *(const float4*)(x + o.x + cbh0);
        vb = *(const float4*)(x + o.x + cbh0 + 4);
        vc = *(const float4*)(x + o.y + cbh0);
        vd = *(const float4*)(x + o.y + cbh0 + 4);

        // MMA ks0
        {
            uint32_t a[2][4];
            LDSM4(a[0], Ab + 0 * 2048 + koffA[0]);
            LDSM4(a[1], Ab + 1 * 2048 + koffA[0]);
            #pragma unroll
            for (int np = 0; np < 4; ++np) {
                uint32_t b[4];
                LDSM4(b, Bb + np * 2048 + koffB[0]);
                #pragma unroll
                for (int mt = 0; mt < 2; ++mt) {
                    mma_f16(acc[mt][np * 2 + 0], a[mt], b);
                    mma_f16(acc[mt][np * 2 + 1], a[mt], b + 2);
                }
            }
        }
        // partial combine half0 (corners 0,1); gather corners 2,3
        c[0] = w.x*va.x + w.y*vc.x; c[1] = w.x*va.y + w.y*vc.y;
        c[2] = w.x*va.z + w.y*vc.z; c[3] = w.x*va.w + w.y*vc.w;
        c[4] = w.x*vb.x + w.y*vd.x; c[5] = w.x*vb.y + w.y*vd.y;
        c[6] = w.x*vb.z + w.y*vd.z; c[7] = w.x*vb.w + w.y*vd.w;
        va = *(const float4*)(x + o.z + cbh0);
        vb = *(const float4*)(x + o.z + cbh0 + 4);
        vc = *(const float4*)(x + o.w + cbh0);
        vd = *(const float4*)(x + o.w + cbh0 + 4);

        // MMA ks1
        {
            uint32_t a[2][4];
            LDSM4(a[0], Ab + 0 * 2048 + koffA[1]);
            LDSM4(a[1], Ab + 1 * 2048 + koffA[1]);
            #pragma unroll
            for (int np = 0; np < 4; ++np) {
                uint32_t b[4];
                LDSM4(b, Bb + np * 2048 + koffB[1]);
                #pragma unroll
                for (int mt = 0; mt < 2; ++mt) {
                    mma_f16(acc[mt][np * 2 + 0], a[mt], b);
                    mma_f16(acc[mt][np * 2 + 1], a[mt], b + 2);
                }
            }
        }
        // finish half0 + STS; gather half1 corners 0,1
        c[0] += w.z*va.x + w.w*vc.x; c[1] += w.z*va.y + w.w*vc.y;
        c[2] += w.z*va.z + w.w*vc.z; c[3] += w.z*va.w + w.w*vc.w;
        c[4] += w.z*vb.x + w.w*vd.x; c[5] += w.z*vb.y + w.w*vd.y;
        c[6] += w.z*vb.z + w.w*vd.z; c[7] += w.z*vb.w + w.w*vd.w;
        {
            __half2 h0 = __floats2half2_rn(c[0], c[1]);
            __half2 h1 = __floats2half2_rn(c[2], c[3]);
            __half2 h2 = __floats2half2_rn(c[4], c[5]);
            __half2 h3 = __floats2half2_rn(c[6], c[7]);
            uint4 st;
            st.x = *(uint32_t*)&h0; st.y = *(uint32_t*)&h1;
            st.z = *(uint32_t*)&h2; st.w = *(uint32_t*)&h3;
            *(uint4*)(smem + Ans + stsoff0) = st;
        }
        const int cbh1 = cbh0 + 8;
        va = *(const float4*)(x + o.x + cbh1);
        vb = *(const float4*)(x + o.x + cbh1 + 4);
        vc = *(const float4*)(x + o.y + cbh1);
        vd = *(const float4*)(x + o.y + cbh1 + 4);

        // MMA ks2
        {
            uint32_t a[2][4];
            LDSM4(a[0], Ab + 0 * 2048 + koffA[2]);
            LDSM4(a[1], Ab + 1 * 2048 + koffA[2]);
            #pragma unroll
            for (int np = 0; np < 4; ++np) {
                uint32_t b[4];
                LDSM4(b, Bb + np * 2048 + koffB[2]);
                #pragma unroll
                for (int mt = 0; mt < 2; ++mt) {
                    mma_f16(acc[mt][np * 2 + 0], a[mt], b);
                    mma_f16(acc[mt][np * 2 + 1], a[mt], b + 2);
                }
            }
        }
        // partial combine half1; gather corners 2,3
        c[0] = w.x*va.x + w.y*vc.x; c[1] = w.x*va.y + w.y*vc.y;
        c[2] = w.x*va.z + w.y*vc.z; c[3] = w.x*va.w + w.y*vc.w;
        c[4] = w.x*vb.x + w.y*vd.x; c[5] = w.x*vb.y + w.y*vd.y;
        c[6] = w.x*vb.z + w.y*vd.z; c[7] = w.x*vb.w + w.y*vd.w;
        va = *(const float4*)(x + o.z + cbh1);
        vb = *(const float4*)(x + o.z + cbh1 + 4);
        vc = *(const float4*)(x + o.w + cbh1);
        vd = *(const float4*)(x + o.w + cbh1 + 4);

        // MMA ks3
        {
            uint32_t a[2][4];
            LDSM4(a[0], Ab + 0 * 2048 + koffA[3]);
            LDSM4(a[1], Ab + 1 * 2048 + koffA[3]);
            #pragma unroll
            for (int np = 0; np < 4; ++np) {
                uint32_t b[4];
                LDSM4(b, Bb + np * 2048 + koffB[3]);
                #pragma unroll
                for (int mt = 0; mt < 2; ++mt) {
                    mma_f16(acc[mt][np * 2 + 0], a[mt], b);
                    mma_f16(acc[mt][np * 2 + 1], a[mt], b + 2);
                }
            }
        }
        // finish half1 + STS
        c[0] += w.z*va.x + w.w*vc.x; c[1] += w.z*va.y + w.w*vc.y;
        c[2] += w.z*va.z + w.w*vc.z; c[3] += w.z*va.w + w.w*vc.w;
        c[4] += w.z*vb.x + w.w*vd.x; c[5] += w.z*vb.y + w.w*vd.y;
        c[6] += w.z*vb.z + w.w*vd.z; c[7] += w.z*vb.w + w.w*vd.w;
        {
            __half2 h0 = __floats2half2_rn(c[0], c[1]);
            __half2 h1 = __floats2half2_rn(c[2], c[3]);
            __half2 h2 = __floats2half2_rn(c[4], c[5]);
            __half2 h3 = __floats2half2_rn(c[6], c[7]);
            uint4 st;
            st.x = *(uint32_t*)&h0; st.y = *(uint32_t*)&h1;
            st.z = *(uint32_t*)&h2; st.w = *(uint32_t*)&h3;
            *(uint4*)(smem + Ans + stsoff1) = st;
        }

        if ((j + 2) < 36 && ((j + 2) & 3) == 0 && tid < 128) {
            const int kp = (j + 2) >> 2, pb = kp & 1;
            compute_params3(kp, m0 + tid, SW0 + pb * 128 + tid, SO0 + pb * 128 + tid);
        }
        CP_WAIT0();
        __syncthreads();
    }

    // ---------------- Final consume: chunk 35 (stage 1) ----------------
    {
        const uint32_t Ab = sb + SM_A + 1 * 16384 + rowAoff;
        const uint32_t Bb = sb + SM_B + 1 * 32768 + rowBoff;
        #pragma unroll
        for (int ks = 0; ks < 4; ++ks) {
            uint32_t a[2][4];
            LDSM4(a[0], Ab + 0 * 2048 + koffA[ks]);
            LDSM4(a[1], Ab + 1 * 2048 + koffA[ks]);
            #pragma unroll
            for (int np = 0; np < 4; ++np) {
                uint32_t b[4];
                LDSM4(b, Bb + np * 2048 + koffB[ks]);
                #pragma unroll
                for (int mt = 0; mt < 2; ++mt) {
                    mma_f16(acc[mt][np * 2 + 0], a[mt], b);
                    mma_f16(acc[mt][np * 2 + 1], a[mt], b + 2);
                }
            }
        }
    }

    // ---------------- Epilogue: bias + store ----------------
    const int g = lane >> 2, cq = lane & 3;
    #pragma unroll
    for (int nt = 0; nt < 8; ++nt) {
        const int fl = wn * 64 + (nt >> 1) * 16 + (nt & 1) * 8 + 2 * cq;
        const float2 bv = *(const float2*)(bias + fl);
        #pragma unroll
        for (int mt = 0; mt < 2; ++mt) {
            const int r0 = m0 + wm * 32 + mt * 16 + g;
            float2 v0, v1;
            v0.x = acc[mt][nt][0] + bv.x;
            v0.y = acc[mt][nt][1] + bv.y;
            v1.x = acc[mt][nt][2] + bv.x;
            v1.y = acc[mt][nt][3] + bv.y;
            *(float2*)(out + (size_t)r0 * 256 + fl) = v0;
            *(float2*)(out + (size_t)(r0 + 8) * 256 + fl) = v1;
        }
    }
}

// ============================ Launch ============================
extern "C" void kernel_launch(void* const* d_in, const int* in_sizes, int n_in,
                              void* d_out, int out_size) {
    (void)in_sizes; (void)n_in; (void)out_size;
    const float* x    = (const float*)d_in[0];
    const float* omw  = (const float*)d_in[1];
    const float* omb  = (const float*)d_in[2];
    const float* W    = (const float*)d_in[3];
    const float* bias = (const float*)d_in[4];
    float* out = (float*)d_out;

    static bool attr_set = false;
    if (!attr_set) {
        cudaFuncSetAttribute(dcn_mma_kernel,
                             cudaFuncAttributeMaxDynamicSharedMemorySize, SM_TOTAL);
        attr_set = true;
    }

    transpose_w<<<dim3(KTOT / 32, FF / 32), 256>>>(W);
    om_prep_w<<<9, 256>>>(omw);
    om_mma_kernel<<<256, 256>>>(x, omb);
    dcn_mma_kernel<<<256, 512, SM_TOTAL>>>(x, bias, out);
}

// round 15
// speedup vs baseline: 1.5045x; 1.5045x over previous
#include <cuda_runtime.h>
#include <cuda_fp16.h>
#include <cstdint>
#include <math.h>

// Problem constants (fixed by the dataset)
#define BB 8
#define HH 64
#define WW 64
#define CC 256
#define FF 256
#define NPIX (BB*HH*WW)   // 32768
#define KTOT 2304         // 9*256

__device__ float g_om[NPIX * 27];
__device__ __half g_Wh[FF * KTOT];     // main weights transposed: Wh[f][k]
__device__ __half g_OMWh[32 * KTOT];   // om weights: OMWh[f][tap*256+c], f 27..31 = 0
__device__ __half g_xh[NPIX * CC];     // fp16 copy of input x

// ============================ helpers ============================
__device__ __forceinline__ uint32_t smem_u32(const void* p) {
    uint32_t a;
    asm("{ .reg .u64 t; cvta.to.shared.u64 t, %1; cvt.u32.u64 %0, t; }"
        : "=r"(a) : "l"(p));
    return a;
}
#define CP_ASYNC16(dst, src) \
    asm volatile("cp.async.cg.shared.global [%0], [%1], 16;" :: "r"(dst), "l"(src) : "memory")
#define CP_COMMIT() asm volatile("cp.async.commit_group;" ::: "memory")
#define CP_WAIT0()  asm volatile("cp.async.wait_group 0;" ::: "memory")

#define LDSM4(r, a) \
    asm volatile("ldmatrix.sync.aligned.m8n8.x4.shared.b16 {%0,%1,%2,%3}, [%4];" \
        : "=r"((r)[0]), "=r"((r)[1]), "=r"((r)[2]), "=r"((r)[3]) : "r"(a))

__device__ __forceinline__ void mma_f16(float* c, const uint32_t* a, const uint32_t* b) {
    asm volatile("mma.sync.aligned.m16n8k16.row.col.f32.f16.f16.f32 "
        "{%0,%1,%2,%3}, {%4,%5,%6,%7}, {%8,%9}, {%0,%1,%2,%3};"
        : "+f"(c[0]), "+f"(c[1]), "+f"(c[2]), "+f"(c[3])
        : "r"(a[0]), "r"(a[1]), "r"(a[2]), "r"(a[3]), "r"(b[0]), "r"(b[1]));
}

// Convert 8 packed halves (uint4) to 8 floats.
__device__ __forceinline__ void h8_to_f8(const uint4& r, float* f) {
    const __half2* h = (const __half2*)&r;
    float2 a = __half22float2(h[0]);
    float2 b = __half22float2(h[1]);
    float2 c = __half22float2(h[2]);
    float2 d = __half22float2(h[3]);
    f[0] = a.x; f[1] = a.y; f[2] = b.x; f[3] = b.y;
    f[4] = c.x; f[5] = c.y; f[6] = d.x; f[7] = d.y;
}

// ============================ Kernel 0a: main W transpose + fp16 ==============
__global__ __launch_bounds__(256) void transpose_w(const float* __restrict__ W) {
    __shared__ float t[32][33];
    int k0 = blockIdx.x * 32, f0 = blockIdx.y * 32;
    int tx = threadIdx.x & 31, ty = threadIdx.x >> 5;
    #pragma unroll
    for (int r = 0; r < 32; r += 8)
        t[ty + r][tx] = W[(k0 + ty + r) * 256 + f0 + tx];
    __syncthreads();
    #pragma unroll
    for (int r = 0; r < 32; r += 8)
        g_Wh[(f0 + ty + r) * KTOT + k0 + tx] = __float2half_rn(t[tx][ty + r]);
}

// ============================ Kernel 0b: om W prep (27->32 pad, fp16) =========
__global__ __launch_bounds__(256) void om_prep_w(const float* __restrict__ omw) {
    int k = blockIdx.x * 256 + threadIdx.x;   // 0..2303
    if (k < KTOT) {
        #pragma unroll
        for (int f = 0; f < 32; ++f) {
            float v = (f < 27) ? omw[k * 27 + f] : 0.f;
            g_OMWh[f * KTOT + k] = __float2half_rn(v);
        }
    }
}

// ============================ Kernel 0c: x -> fp16 ============================
__global__ __launch_bounds__(256) void x_to_h(const float* __restrict__ x) {
    const int i = (blockIdx.x * 256 + threadIdx.x) * 8;   // 8 floats per thread
    float4 a = *(const float4*)(x + i);
    float4 b = *(const float4*)(x + i + 4);
    __half2 h0 = __floats2half2_rn(a.x, a.y);
    __half2 h1 = __floats2half2_rn(a.z, a.w);
    __half2 h2 = __floats2half2_rn(b.x, b.y);
    __half2 h3 = __floats2half2_rn(b.z, b.w);
    uint4 st;
    st.x = *(uint32_t*)&h0; st.y = *(uint32_t*)&h1;
    st.z = *(uint32_t*)&h2; st.w = *(uint32_t*)&h3;
    *(uint4*)(g_xh + i) = st;
}

// ============================ Kernel 1: om conv via fp16 mma ==================
// M=128 pixels/CTA (grid 256), N=32 (27 used), K=2304 in 72 chunks of 32.
__global__ __launch_bounds__(256, 1) void om_mma_kernel(const float* __restrict__ omb) {
    __shared__ __align__(16) char smem[2 * 8192 + 2 * 2048];   // A 16KB + B 4KB
    const uint32_t sb = smem_u32(smem);
    const uint32_t A_OFF = 0, B_OFF = 16384;
    const int tid = threadIdx.x;
    const int lane = tid & 31, wid = tid >> 5;
    const int m0 = blockIdx.x * 128;

    float acc[4][4];
    #pragma unroll
    for (int nt = 0; nt < 4; ++nt)
        #pragma unroll
        for (int q = 0; q < 4; ++q) acc[nt][q] = 0.f;

    const int rA = wid * 16 + (lane & 7) + ((lane >> 3) & 1) * 8;
    const int kbitA = lane >> 4;
    const int rB = (lane & 7) + (lane >> 4) * 8;
    const int kbitB = (lane >> 3) & 1;
    uint32_t koffA[2], koffB[2];
    #pragma unroll
    for (int ks = 0; ks < 2; ++ks) {
        koffA[ks] = (uint32_t)(((ks * 2 + kbitA) ^ ((rA >> 1) & 3)) * 16);
        koffB[ks] = (uint32_t)(((ks * 2 + kbitB) ^ ((rB >> 1) & 3)) * 16);
    }
    const uint32_t rowAoff = (uint32_t)(rA * 64);
    const uint32_t rowBoff = (uint32_t)(rB * 64);

    const int px = tid >> 1, half = tid & 1;
    const int m = m0 + px;
    const int y = (m >> 6) & 63, xc = m & 63, b = m >> 12;

    auto stageA = [&](int j, int stage) {
        const int tap = j >> 3;
        const int ky = tap / 3, kx = tap - ky * 3;
        const int sy = y - 1 + ky, sx = xc - 1 + kx;
        const bool valid = ((unsigned)sy < 64u) && ((unsigned)sx < 64u);
        uint4 s0 = {0,0,0,0}, s1 = {0,0,0,0};
        if (valid) {
            const __half* src = g_xh + (((b << 12) + sy * 64 + sx) << 8)
                                + (j & 7) * 32 + half * 16;
            s0 = *(const uint4*)(src);
            s1 = *(const uint4*)(src + 8);
        }
        const int g0 = half * 2, ss = (px >> 1) & 3;
        char* base = smem + A_OFF + stage * 8192 + px * 64;
        *(uint4*)(base + ((g0 ^ ss) * 16)) = s0;
        *(uint4*)(base + (((g0 + 1) ^ ss) * 16)) = s1;
    };
    auto stageB = [&](int j, int stage) {
        if (tid < 128) {
            const int n = tid >> 2, g = tid & 3;
            const uint32_t dst = sb + B_OFF + stage * 2048 + n * 64
                                 + ((g ^ ((n >> 1) & 3)) * 16);
            CP_ASYNC16(dst, g_OMWh + (size_t)n * KTOT + j * 32 + g * 8);
        }
    };

    stageB(0, 0);
    CP_COMMIT();
    stageA(0, 0);
    CP_WAIT0();
    __syncthreads();

    for (int j = 0; j < 72; ++j) {
        const int s = j & 1, ns = s ^ 1;
        if (j < 71) {
            stageB(j + 1, ns);
            CP_COMMIT();
            stageA(j + 1, ns);
        }
        const uint32_t Ab = sb + A_OFF + s * 8192 + rowAoff;
        const uint32_t Bb = sb + B_OFF + s * 2048 + rowBoff;
        #pragma unroll
        for (int ks = 0; ks < 2; ++ks) {
            uint32_t a[4];
            LDSM4(a, Ab + koffA[ks]);
            uint32_t b0[4], b1[4];
            LDSM4(b0, Bb + 0 * 1024 + koffB[ks]);
            LDSM4(b1, Bb + 1 * 1024 + koffB[ks]);
            mma_f16(acc[0], a, b0);
            mma_f16(acc[1], a, b0 + 2);
            mma_f16(acc[2], a, b1);
            mma_f16(acc[3], a, b1 + 2);
        }
        if (j < 71) CP_WAIT0();
        __syncthreads();
    }

    const int g = lane >> 2, cq = lane & 3;
    #pragma unroll
    for (int nt = 0; nt < 4; ++nt) {
        #pragma unroll
        for (int q = 0; q < 4; ++q) {
            const int f = nt * 8 + 2 * cq + (q & 1);
            if (f < 27) {
                const int row = m0 + wid * 16 + g + ((q >> 1) * 8);
                float v = acc[nt][q] + omb[f];
                if (f >= 18) v = 2.f / (1.f + expf(-v));
                g_om[row * 27 + f] = v;
            }
        }
    }
}

// ============================ Kernel 2: fused sampling + fp16 mma GEMM ========
// CTA: 512 threads (16 warps), tile M=128 x N=256. Grid 256 m-tiles.
// Warps: 4(m) x 4(n), warp tile 32x64, fp16 m16n8k16, acc[2 mt][8 nt][4] f32.
// 72 K-chunks of 32 fp16; 2 smem stages; fp16 gathers for j+1 pipelined
// through the MMA blocks of chunk j.
#define SM_SW 0              // [2][128] float4 bilinear weights (4KB)
#define SM_SO 4096           // [2][128] int4 corner offsets (4KB)
#define SM_A  8192           // [2][128][64B] fp16 (16KB)
#define SM_B  24576          // [2][256][64B] fp16 (32KB)
#define SM_TOTAL 57344

__device__ __forceinline__ void compute_params3(int kp, int m, float4* sw4, int4* so4) {
    const float* omp = g_om + m * 27;
    const int y = (m >> 6) & 63, xc = m & 63, b = m >> 12;
    const int ky = kp / 3, kx = kp - ky * 3;
    float py = (float)(y - 1 + ky) + omp[2 * kp];
    float px = (float)(xc - 1 + kx) + omp[2 * kp + 1];
    float msk = omp[18 + kp];
    float y0f = floorf(py), x0f = floorf(px);
    float wy1 = py - y0f, wy0 = 1.f - wy1;
    float wx1 = px - x0f, wx0 = 1.f - wx1;
    int iy0 = (int)y0f, ix0 = (int)x0f;
    int iy1 = iy0 + 1, ix1 = ix0 + 1;
    bool vy0 = (unsigned)iy0 < 64u, vy1 = (unsigned)iy1 < 64u;
    bool vx0 = (unsigned)ix0 < 64u, vx1 = (unsigned)ix1 < 64u;
    int cy0 = min(max(iy0, 0), 63), cy1 = min(max(iy1, 0), 63);
    int cx0 = min(max(ix0, 0), 63), cx1 = min(max(ix1, 0), 63);
    int base = b << 12;
    int4 o;
    o.x = (base + cy0 * 64 + cx0) << 8;
    o.y = (base + cy0 * 64 + cx1) << 8;
    o.z = (base + cy1 * 64 + cx0) << 8;
    o.w = (base + cy1 * 64 + cx1) << 8;
    float4 w;
    w.x = (vy0 && vx0) ? wy0 * wx0 * msk : 0.f;
    w.y = (vy0 && vx1) ? wy0 * wx1 * msk : 0.f;
    w.z = (vy1 && vx0) ? wy1 * wx0 * msk : 0.f;
    w.w = (vy1 && vx1) ? wy1 * wx1 * msk : 0.f;
    *so4 = o;
    *sw4 = w;
}

// Stage B chunk j with 512 threads: n = tid>>1, two 16B granules each.
__device__ __forceinline__ void loadB3(uint32_t sb, int j, int stage, int tid) {
    const int n = tid >> 1, g0 = (tid & 1) * 2;
    const int ss = (n >> 1) & 3;
    const uint32_t dbase = sb + SM_B + stage * 16384 + n * 64;
    const __half* src = g_Wh + (size_t)n * KTOT + j * 32;
    CP_ASYNC16(dbase + ((g0 ^ ss) * 16), src + g0 * 8);
    CP_ASYNC16(dbase + (((g0 + 1) ^ ss) * 16), src + (g0 + 1) * 8);
}

__global__ __launch_bounds__(512, 1) void dcn_mma_kernel(
    const float* __restrict__ bias,   // [256]
    float* __restrict__ out)          // [32768,256]
{
    extern __shared__ char smem[];
    const uint32_t sb = smem_u32(smem);
    const int tid = threadIdx.x;
    const int lane = tid & 31, wid = tid >> 5;
    const int wm = wid & 3, wn = wid >> 2;     // 4m x 4n
    const int m0 = blockIdx.x * 128;

    float4* SW0 = (float4*)(smem + SM_SW);
    int4*   SO0 = (int4*)(smem + SM_SO);

    float acc[2][8][4];
    #pragma unroll
    for (int mt = 0; mt < 2; ++mt)
        #pragma unroll
        for (int nt = 0; nt < 8; ++nt)
            #pragma unroll
            for (int q = 0; q < 4; ++q) acc[mt][nt][q] = 0.f;

    // ldmatrix addressing
    const int rA = wm * 32 + (lane & 7) + ((lane >> 3) & 1) * 8;
    const int kbitA = lane >> 4;
    const int rB = wn * 64 + (lane & 7) + (lane >> 4) * 8;
    const int kbitB = (lane >> 3) & 1;
    uint32_t koffA[2], koffB[2];
    #pragma unroll
    for (int ks = 0; ks < 2; ++ks) {
        koffA[ks] = (uint32_t)(((ks * 2 + kbitA) ^ ((rA >> 1) & 3)) * 16);
        koffB[ks] = (uint32_t)(((ks * 2 + kbitB) ^ ((rB >> 1) & 3)) * 16);
    }
    const uint32_t rowAoff = (uint32_t)(rA * 64);
    const uint32_t rowBoff = (uint32_t)(rB * 64);

    // sampling identity: 4 threads per pixel, thread owns 8 channels
    const int spx = tid >> 2, sq = tid & 3;
    const uint32_t stsoff = (uint32_t)(spx * 64 + ((sq ^ ((spx >> 1) & 3)) * 16));

    // ---------------- Prologue ----------------
    if (tid < 128) compute_params3(0, m0 + tid, SW0 + tid, SO0 + tid);
    __syncthreads();
    loadB3(sb, 0, 0, tid);
    CP_COMMIT();
    {
        const int cb = sq * 8;
        const int4 o = SO0[spx];
        const float4 w = SW0[spx];
        uint4 r0 = *(const uint4*)(g_xh + o.x + cb);
        uint4 r1 = *(const uint4*)(g_xh + o.y + cb);
        uint4 r2 = *(const uint4*)(g_xh + o.z + cb);
        uint4 r3 = *(const uint4*)(g_xh + o.w + cb);
        float f0[8], f1[8], f2[8], f3[8], c[8];
        h8_to_f8(r0, f0); h8_to_f8(r1, f1); h8_to_f8(r2, f2); h8_to_f8(r3, f3);
        #pragma unroll
        for (int i = 0; i < 8; ++i)
            c[i] = w.x * f0[i] + w.y * f1[i] + w.z * f2[i] + w.w * f3[i];
        __half2 h0 = __floats2half2_rn(c[0], c[1]);
        __half2 h1 = __floats2half2_rn(c[2], c[3]);
        __half2 h2 = __floats2half2_rn(c[4], c[5]);
        __half2 h3 = __floats2half2_rn(c[6], c[7]);
        uint4 st;
        st.x = *(uint32_t*)&h0; st.y = *(uint32_t*)&h1;
        st.z = *(uint32_t*)&h2; st.w = *(uint32_t*)&h3;
        *(uint4*)(smem + SM_A + stsoff) = st;
    }
    CP_WAIT0();
    __syncthreads();

    // ---------------- Main loop: consume j, produce j+1 ----------------
    for (int j = 0; j < 71; ++j) {
        const int s = j & 1, ns = s ^ 1;
        const int pb1 = ((j + 1) >> 3) & 1;
        const float4* SWn = SW0 + pb1 * 128;
        const int4*   SOn = SO0 + pb1 * 128;
        const int cb = ((j + 1) & 7) * 32 + sq * 8;
        const uint32_t Ans = (uint32_t)(SM_A + ns * 8192);

        loadB3(sb, j + 1, ns, tid);
        CP_COMMIT();

        const uint32_t Ab = sb + SM_A + s * 8192 + rowAoff;
        const uint32_t Bb = sb + SM_B + s * 16384 + rowBoff;

        const int4 o = SOn[spx];
        const float4 w = SWn[spx];

        // gather corners 0,1 (fp16, 1 LDG.128 each)
        uint4 r0 = *(const uint4*)(g_xh + o.x + cb);
        uint4 r1 = *(const uint4*)(g_xh + o.y + cb);

        // ks0: A + B np0/1, acc nt0..3
        uint32_t a0[2][4];
        LDSM4(a0[0], Ab + 0 * 1024 + koffA[0]);
        LDSM4(a0[1], Ab + 1 * 1024 + koffA[0]);
        {
            uint32_t b0[4], b1[4];
            LDSM4(b0, Bb + 0 * 1024 + koffB[0]);
            LDSM4(b1, Bb + 1 * 1024 + koffB[0]);
            #pragma unroll
            for (int mt = 0; mt < 2; ++mt) {
                mma_f16(acc[mt][0], a0[mt], b0);
                mma_f16(acc[mt][1], a0[mt], b0 + 2);
                mma_f16(acc[mt][2], a0[mt], b1);
                mma_f16(acc[mt][3], a0[mt], b1 + 2);
            }
        }
        // partial combine with corners 0,1
        float fa[8], fb[8], c[8];
        h8_to_f8(r0, fa); h8_to_f8(r1, fb);
        #pragma unroll
        for (int i = 0; i < 8; ++i) c[i] = w.x * fa[i] + w.y * fb[i];
        // gather corners 2,3
        uint4 r2 = *(const uint4*)(g_xh + o.z + cb);
        uint4 r3 = *(const uint4*)(g_xh + o.w + cb);

        // ks0: B np2/3, acc nt4..7
        {
            uint32_t b0[4], b1[4];
            LDSM4(b0, Bb + 2 * 1024 + koffB[0]);
            LDSM4(b1, Bb + 3 * 1024 + koffB[0]);
            #pragma unroll
            for (int mt = 0; mt < 2; ++mt) {
                mma_f16(acc[mt][4], a0[mt], b0);
                mma_f16(acc[mt][5], a0[mt], b0 + 2);
                mma_f16(acc[mt][6], a0[mt], b1);
                mma_f16(acc[mt][7], a0[mt], b1 + 2);
            }
        }
        // finish combine + STS
        h8_to_f8(r2, fa); h8_to_f8(r3, fb);
        #pragma unroll
        for (int i = 0; i < 8; ++i) c[i] += w.z * fa[i] + w.w * fb[i];
        {
            __half2 h0 = __floats2half2_rn(c[0], c[1]);
            __half2 h1 = __floats2half2_rn(c[2], c[3]);
            __half2 h2 = __floats2half2_rn(c[4], c[5]);
            __half2 h3 = __floats2half2_rn(c[6], c[7]);
            uint4 st;
            st.x = *(uint32_t*)&h0; st.y = *(uint32_t*)&h1;
            st.z = *(uint32_t*)&h2; st.w = *(uint32_t*)&h3;
            *(uint4*)(smem + Ans + stsoff) = st;
        }
        // ks1: full block
        {
            uint32_t a1[2][4];
            LDSM4(a1[0], Ab + 0 * 1024 + koffA[1]);
            LDSM4(a1[1], Ab + 1 * 1024 + koffA[1]);
            #pragma unroll
            for (int np = 0; np < 4; ++np) {
                uint32_t b[4];
                LDSM4(b, Bb + np * 1024 + koffB[1]);
                #pragma unroll
                for (int mt = 0; mt < 2; ++mt) {
                    mma_f16(acc[mt][np * 2 + 0], a1[mt], b);
                    mma_f16(acc[mt][np * 2 + 1], a1[mt], b + 2);
                }
            }
        }

        if ((j + 2) < 72 && ((j + 2) & 7) == 0 && tid < 128) {
            const int kp = (j + 2) >> 3, pb = kp & 1;
            compute_params3(kp, m0 + tid, SW0 + pb * 128 + tid, SO0 + pb * 128 + tid);
        }
        CP_WAIT0();
        __syncthreads();
    }

    // ---------------- Final consume: chunk 71 (stage 1) ----------------
    {
        const uint32_t Ab = sb + SM_A + 1 * 8192 + rowAoff;
        const uint32_t Bb = sb + SM_B + 1 * 16384 + rowBoff;
        #pragma unroll
        for (int ks = 0; ks < 2; ++ks) {
            uint32_t a[2][4];
            LDSM4(a[0], Ab + 0 * 1024 + koffA[ks]);
            LDSM4(a[1], Ab + 1 * 1024 + koffA[ks]);
            #pragma unroll
            for (int np = 0; np < 4; ++np) {
                uint32_t b[4];
                LDSM4(b, Bb + np * 1024 + koffB[ks]);
                #pragma unroll
                for (int mt = 0; mt < 2; ++mt) {
                    mma_f16(acc[mt][np * 2 + 0], a[mt], b);
                    mma_f16(acc[mt][np * 2 + 1], a[mt], b + 2);
                }
            }
        }
    }

    // ---------------- Epilogue: bias + store ----------------
    const int g = lane >> 2, cq = lane & 3;
    #pragma unroll
    for (int nt = 0; nt < 8; ++nt) {
        const int fl = wn * 64 + (nt >> 1) * 16 + (nt & 1) * 8 + 2 * cq;
        const float2 bv = *(const float2*)(bias + fl);
        #pragma unroll
        for (int mt = 0; mt < 2; ++mt) {
            const int r0 = m0 + wm * 32 + mt * 16 + g;
            float2 v0, v1;
            v0.x = acc[mt][nt][0] + bv.x;
            v0.y = acc[mt][nt][1] + bv.y;
            v1.x = acc[mt][nt][2] + bv.x;
            v1.y = acc[mt][nt][3] + bv.y;
            *(float2*)(out + (size_t)r0 * 256 + fl) = v0;
            *(float2*)(out + (size_t)(r0 + 8) * 256 + fl) = v1;
        }
    }
}

// ============================ Launch ============================
extern "C" void kernel_launch(void* const* d_in, const int* in_sizes, int n_in,
                              void* d_out, int out_size) {
    (void)in_sizes; (void)n_in; (void)out_size;
    const float* x    = (const float*)d_in[0];
    const float* omw  = (const float*)d_in[1];
    const float* omb  = (const float*)d_in[2];
    const float* W    = (const float*)d_in[3];
    const float* bias = (const float*)d_in[4];
    float* out = (float*)d_out;

    static bool attr_set = false;
    if (!attr_set) {
        cudaFuncSetAttribute(dcn_mma_kernel,
                             cudaFuncAttributeMaxDynamicSharedMemorySize, SM_TOTAL);
        attr_set = true;
    }

    x_to_h<<<NPIX * CC / (256 * 8), 256>>>(x);
    transpose_w<<<dim3(KTOT / 32, FF / 32), 256>>>(W);
    om_prep_w<<<9, 256>>>(omw);
    om_mma_kernel<<<256, 256>>>(omb);
    dcn_mma_kernel<<<256, 512, SM_TOTAL>>>(bias, out);
}

// round 16
// speedup vs baseline: 1.5983x; 1.0623x over previous
#include <cuda_runtime.h>
#include <cuda_fp16.h>
#include <cstdint>
#include <math.h>

// Problem constants (fixed by the dataset)
#define BB 8
#define HH 64
#define WW 64
#define CC 256
#define FF 256
#define NPIX (BB*HH*WW)   // 32768
#define KTOT 2304         // 9*256

__device__ float g_om[NPIX * 27];
__device__ __half g_Wh[FF * KTOT];     // main weights transposed: Wh[f][k]
__device__ __half g_OMWh[32 * KTOT];   // om weights: OMWh[f][tap*256+c], f 27..31 = 0
__device__ __half g_xh[NPIX * CC];     // fp16 copy of input x

// ============================ helpers ============================
__device__ __forceinline__ uint32_t smem_u32(const void* p) {
    uint32_t a;
    asm("{ .reg .u64 t; cvta.to.shared.u64 t, %1; cvt.u32.u64 %0, t; }"
        : "=r"(a) : "l"(p));
    return a;
}
#define CP_ASYNC16(dst, src) \
    asm volatile("cp.async.cg.shared.global [%0], [%1], 16;" :: "r"(dst), "l"(src) : "memory")
#define CP_ASYNC16Z(dst, src, sz) \
    asm volatile("cp.async.cg.shared.global [%0], [%1], 16, %2;" \
                 :: "r"(dst), "l"(src), "r"(sz) : "memory")
#define CP_COMMIT() asm volatile("cp.async.commit_group;" ::: "memory")
#define CP_WAIT0()  asm volatile("cp.async.wait_group 0;" ::: "memory")

#define LDSM4(r, a) \
    asm volatile("ldmatrix.sync.aligned.m8n8.x4.shared.b16 {%0,%1,%2,%3}, [%4];" \
        : "=r"((r)[0]), "=r"((r)[1]), "=r"((r)[2]), "=r"((r)[3]) : "r"(a))

__device__ __forceinline__ void mma_f16(float* c, const uint32_t* a, const uint32_t* b) {
    asm volatile("mma.sync.aligned.m16n8k16.row.col.f32.f16.f16.f32 "
        "{%0,%1,%2,%3}, {%4,%5,%6,%7}, {%8,%9}, {%0,%1,%2,%3};"
        : "+f"(c[0]), "+f"(c[1]), "+f"(c[2]), "+f"(c[3])
        : "r"(a[0]), "r"(a[1]), "r"(a[2]), "r"(a[3]), "r"(b[0]), "r"(b[1]));
}

// Convert 8 packed halves (uint4) to 8 floats.
__device__ __forceinline__ void h8_to_f8(const uint4& r, float* f) {
    const __half2* h = (const __half2*)&r;
    float2 a = __half22float2(h[0]);
    float2 b = __half22float2(h[1]);
    float2 c = __half22float2(h[2]);
    float2 d = __half22float2(h[3]);
    f[0] = a.x; f[1] = a.y; f[2] = b.x; f[3] = b.y;
    f[4] = c.x; f[5] = c.y; f[6] = d.x; f[7] = d.y;
}

// ============================ Kernel 0a: main W transpose + fp16 ==============
__global__ __launch_bounds__(256) void transpose_w(const float* __restrict__ W) {
    __shared__ float t[32][33];
    int k0 = blockIdx.x * 32, f0 = blockIdx.y * 32;
    int tx = threadIdx.x & 31, ty = threadIdx.x >> 5;
    #pragma unroll
    for (int r = 0; r < 32; r += 8)
        t[ty + r][tx] = W[(k0 + ty + r) * 256 + f0 + tx];
    __syncthreads();
    #pragma unroll
    for (int r = 0; r < 32; r += 8)
        g_Wh[(f0 + ty + r) * KTOT + k0 + tx] = __float2half_rn(t[tx][ty + r]);
}

// ============================ Kernel 0b: om W prep (27->32 pad, fp16) =========
__global__ __launch_bounds__(256) void om_prep_w(const float* __restrict__ omw) {
    int k = blockIdx.x * 256 + threadIdx.x;   // 0..2303
    if (k < KTOT) {
        #pragma unroll
        for (int f = 0; f < 32; ++f) {
            float v = (f < 27) ? omw[k * 27 + f] : 0.f;
            g_OMWh[f * KTOT + k] = __float2half_rn(v);
        }
    }
}

// ============================ Kernel 0c: x -> fp16 ============================
__global__ __launch_bounds__(256) void x_to_h(const float* __restrict__ x) {
    const int i = (blockIdx.x * 256 + threadIdx.x) * 8;   // 8 floats per thread
    float4 a = *(const float4*)(x + i);
    float4 b = *(const float4*)(x + i + 4);
    __half2 h0 = __floats2half2_rn(a.x, a.y);
    __half2 h1 = __floats2half2_rn(a.z, a.w);
    __half2 h2 = __floats2half2_rn(b.x, b.y);
    __half2 h3 = __floats2half2_rn(b.z, b.w);
    uint4 st;
    st.x = *(uint32_t*)&h0; st.y = *(uint32_t*)&h1;
    st.z = *(uint32_t*)&h2; st.w = *(uint32_t*)&h3;
    *(uint4*)(g_xh + i) = st;
}

// ============================ Kernel 1: om conv via fp16 mma ==================
// M=128 pixels/CTA (grid 256), N=32 (27 used), K=2304 in 72 chunks of 32.
// A staged via cp.async with src-size zero fill (no branches, no reg round-trip).
__global__ __launch_bounds__(256, 1) void om_mma_kernel(const float* __restrict__ omb) {
    __shared__ __align__(16) char smem[2 * 8192 + 2 * 2048];   // A 16KB + B 4KB
    const uint32_t sb = smem_u32(smem);
    const uint32_t A_OFF = 0, B_OFF = 16384;
    const int tid = threadIdx.x;
    const int lane = tid & 31, wid = tid >> 5;
    const int m0 = blockIdx.x * 128;

    float acc[4][4];
    #pragma unroll
    for (int nt = 0; nt < 4; ++nt)
        #pragma unroll
        for (int q = 0; q < 4; ++q) acc[nt][q] = 0.f;

    const int rA = wid * 16 + (lane & 7) + ((lane >> 3) & 1) * 8;
    const int kbitA = lane >> 4;
    const int rB = (lane & 7) + (lane >> 4) * 8;
    const int kbitB = (lane >> 3) & 1;
    uint32_t koffA[2], koffB[2];
    #pragma unroll
    for (int ks = 0; ks < 2; ++ks) {
        koffA[ks] = (uint32_t)(((ks * 2 + kbitA) ^ ((rA >> 1) & 3)) * 16);
        koffB[ks] = (uint32_t)(((ks * 2 + kbitB) ^ ((rB >> 1) & 3)) * 16);
    }
    const uint32_t rowAoff = (uint32_t)(rA * 64);
    const uint32_t rowBoff = (uint32_t)(rB * 64);

    const int px = tid >> 1, half = tid & 1;
    const int m = m0 + px;
    const int y = (m >> 6) & 63, xc = m & 63, b = m >> 12;

    auto stageA = [&](int j, int stage) {
        const int tap = j >> 3;
        const int ky = tap / 3, kx = tap - ky * 3;
        const int sy = y - 1 + ky, sx = xc - 1 + kx;
        const bool valid = ((unsigned)sy < 64u) && ((unsigned)sx < 64u);
        const int csy = min(max(sy, 0), 63), csx = min(max(sx, 0), 63);
        const __half* src = g_xh + (((b << 12) + csy * 64 + csx) << 8)
                            + (j & 7) * 32 + half * 16;
        const int sz = valid ? 16 : 0;
        const int g0 = half * 2, ss = (px >> 1) & 3;
        const uint32_t base = sb + A_OFF + stage * 8192 + px * 64;
        CP_ASYNC16Z(base + ((g0 ^ ss) * 16), src, sz);
        CP_ASYNC16Z(base + (((g0 + 1) ^ ss) * 16), src + 8, sz);
    };
    auto stageB = [&](int j, int stage) {
        if (tid < 128) {
            const int n = tid >> 2, g = tid & 3;
            const uint32_t dst = sb + B_OFF + stage * 2048 + n * 64
                                 + ((g ^ ((n >> 1) & 3)) * 16);
            CP_ASYNC16(dst, g_OMWh + (size_t)n * KTOT + j * 32 + g * 8);
        }
    };

    stageB(0, 0);
    stageA(0, 0);
    CP_COMMIT();
    CP_WAIT0();
    __syncthreads();

    for (int j = 0; j < 72; ++j) {
        const int s = j & 1, ns = s ^ 1;
        if (j < 71) {
            stageB(j + 1, ns);
            stageA(j + 1, ns);
            CP_COMMIT();
        }
        const uint32_t Ab = sb + A_OFF + s * 8192 + rowAoff;
        const uint32_t Bb = sb + B_OFF + s * 2048 + rowBoff;
        #pragma unroll
        for (int ks = 0; ks < 2; ++ks) {
            uint32_t a[4];
            LDSM4(a, Ab + koffA[ks]);
            uint32_t b0[4], b1[4];
            LDSM4(b0, Bb + 0 * 1024 + koffB[ks]);
            LDSM4(b1, Bb + 1 * 1024 + koffB[ks]);
            mma_f16(acc[0], a, b0);
            mma_f16(acc[1], a, b0 + 2);
            mma_f16(acc[2], a, b1);
            mma_f16(acc[3], a, b1 + 2);
        }
        if (j < 71) CP_WAIT0();
        __syncthreads();
    }

    const int g = lane >> 2, cq = lane & 3;
    #pragma unroll
    for (int nt = 0; nt < 4; ++nt) {
        #pragma unroll
        for (int q = 0; q < 4; ++q) {
            const int f = nt * 8 + 2 * cq + (q & 1);
            if (f < 27) {
                const int row = m0 + wid * 16 + g + ((q >> 1) * 8);
                float v = acc[nt][q] + omb[f];
                if (f >= 18) v = 2.f / (1.f + expf(-v));
                g_om[row * 27 + f] = v;
            }
        }
    }
}

// ============================ Kernel 2: fused sampling + fp16 mma GEMM ========
// CTA: 512 threads (16 warps), tile M=128 x N=256. Grid 256 m-tiles.
// Warps: 4(m) x 4(n), warp tile 32x64, fp16 m16n8k16, acc[2 mt][8 nt][4] f32.
// 72 K-chunks of 32 fp16; 2 smem stages; fp16 gathers for j+1 pipelined
// through the MMA blocks of chunk j. Params computed by ALL threads (4-way
// duplicated per pixel) to avoid warp imbalance.
#define SM_SW 0              // [2][128] float4 bilinear weights (4KB)
#define SM_SO 4096           // [2][128] int4 corner offsets (4KB)
#define SM_A  8192           // [2][128][64B] fp16 (16KB)
#define SM_B  24576          // [2][256][64B] fp16 (32KB)
#define SM_TOTAL 57344

__device__ __forceinline__ void compute_params3(int kp, int m, float4* sw4, int4* so4) {
    const float* omp = g_om + m * 27;
    const int y = (m >> 6) & 63, xc = m & 63, b = m >> 12;
    const int ky = kp / 3, kx = kp - ky * 3;
    float py = (float)(y - 1 + ky) + omp[2 * kp];
    float px = (float)(xc - 1 + kx) + omp[2 * kp + 1];
    float msk = omp[18 + kp];
    float y0f = floorf(py), x0f = floorf(px);
    float wy1 = py - y0f, wy0 = 1.f - wy1;
    float wx1 = px - x0f, wx0 = 1.f - wx1;
    int iy0 = (int)y0f, ix0 = (int)x0f;
    int iy1 = iy0 + 1, ix1 = ix0 + 1;
    bool vy0 = (unsigned)iy0 < 64u, vy1 = (unsigned)iy1 < 64u;
    bool vx0 = (unsigned)ix0 < 64u, vx1 = (unsigned)ix1 < 64u;
    int cy0 = min(max(iy0, 0), 63), cy1 = min(max(iy1, 0), 63);
    int cx0 = min(max(ix0, 0), 63), cx1 = min(max(ix1, 0), 63);
    int base = b << 12;
    int4 o;
    o.x = (base + cy0 * 64 + cx0) << 8;
    o.y = (base + cy0 * 64 + cx1) << 8;
    o.z = (base + cy1 * 64 + cx0) << 8;
    o.w = (base + cy1 * 64 + cx1) << 8;
    float4 w;
    w.x = (vy0 && vx0) ? wy0 * wx0 * msk : 0.f;
    w.y = (vy0 && vx1) ? wy0 * wx1 * msk : 0.f;
    w.z = (vy1 && vx0) ? wy1 * wx0 * msk : 0.f;
    w.w = (vy1 && vx1) ? wy1 * wx1 * msk : 0.f;
    *so4 = o;
    *sw4 = w;
}

// Stage B chunk j with 512 threads: n = tid>>1, two 16B granules each.
__device__ __forceinline__ void loadB3(uint32_t sb, int j, int stage, int tid) {
    const int n = tid >> 1, g0 = (tid & 1) * 2;
    const int ss = (n >> 1) & 3;
    const uint32_t dbase = sb + SM_B + stage * 16384 + n * 64;
    const __half* src = g_Wh + (size_t)n * KTOT + j * 32;
    CP_ASYNC16(dbase + ((g0 ^ ss) * 16), src + g0 * 8);
    CP_ASYNC16(dbase + (((g0 + 1) ^ ss) * 16), src + (g0 + 1) * 8);
}

__global__ __launch_bounds__(512, 1) void dcn_mma_kernel(
    const float* __restrict__ bias,   // [256]
    float* __restrict__ out)          // [32768,256]
{
    extern __shared__ char smem[];
    const uint32_t sb = smem_u32(smem);
    const int tid = threadIdx.x;
    const int lane = tid & 31, wid = tid >> 5;
    const int wm = wid & 3, wn = wid >> 2;     // 4m x 4n
    const int m0 = blockIdx.x * 128;

    float4* SW0 = (float4*)(smem + SM_SW);
    int4*   SO0 = (int4*)(smem + SM_SO);

    float acc[2][8][4];
    #pragma unroll
    for (int mt = 0; mt < 2; ++mt)
        #pragma unroll
        for (int nt = 0; nt < 8; ++nt)
            #pragma unroll
            for (int q = 0; q < 4; ++q) acc[mt][nt][q] = 0.f;

    // ldmatrix addressing
    const int rA = wm * 32 + (lane & 7) + ((lane >> 3) & 1) * 8;
    const int kbitA = lane >> 4;
    const int rB = wn * 64 + (lane & 7) + (lane >> 4) * 8;
    const int kbitB = (lane >> 3) & 1;
    uint32_t koffA[2], koffB[2];
    #pragma unroll
    for (int ks = 0; ks < 2; ++ks) {
        koffA[ks] = (uint32_t)(((ks * 2 + kbitA) ^ ((rA >> 1) & 3)) * 16);
        koffB[ks] = (uint32_t)(((ks * 2 + kbitB) ^ ((rB >> 1) & 3)) * 16);
    }
    const uint32_t rowAoff = (uint32_t)(rA * 64);
    const uint32_t rowBoff = (uint32_t)(rB * 64);

    // sampling identity: 4 threads per pixel, thread owns 8 channels
    const int spx = tid >> 2, sq = tid & 3;
    const uint32_t stsoff = (uint32_t)(spx * 64 + ((sq ^ ((spx >> 1) & 3)) * 16));

    // ---------------- Prologue ----------------
    compute_params3(0, m0 + spx, SW0 + spx, SO0 + spx);  // 4-way dup, same data
    __syncthreads();
    loadB3(sb, 0, 0, tid);
    CP_COMMIT();
    {
        const int cb = sq * 8;
        const int4 o = SO0[spx];
        const float4 w = SW0[spx];
        uint4 r0 = *(const uint4*)(g_xh + o.x + cb);
        uint4 r1 = *(const uint4*)(g_xh + o.y + cb);
        uint4 r2 = *(const uint4*)(g_xh + o.z + cb);
        uint4 r3 = *(const uint4*)(g_xh + o.w + cb);
        float f0[8], f1[8], f2[8], f3[8], c[8];
        h8_to_f8(r0, f0); h8_to_f8(r1, f1); h8_to_f8(r2, f2); h8_to_f8(r3, f3);
        #pragma unroll
        for (int i = 0; i < 8; ++i)
            c[i] = w.x * f0[i] + w.y * f1[i] + w.z * f2[i] + w.w * f3[i];
        __half2 h0 = __floats2half2_rn(c[0], c[1]);
        __half2 h1 = __floats2half2_rn(c[2], c[3]);
        __half2 h2 = __floats2half2_rn(c[4], c[5]);
        __half2 h3 = __floats2half2_rn(c[6], c[7]);
        uint4 st;
        st.x = *(uint32_t*)&h0; st.y = *(uint32_t*)&h1;
        st.z = *(uint32_t*)&h2; st.w = *(uint32_t*)&h3;
        *(uint4*)(smem + SM_A + stsoff) = st;
    }
    CP_WAIT0();
    __syncthreads();

    // ---------------- Main loop: consume j, produce j+1 ----------------
    for (int j = 0; j < 71; ++j) {
        const int s = j & 1, ns = s ^ 1;
        const int pb1 = ((j + 1) >> 3) & 1;
        const float4* SWn = SW0 + pb1 * 128;
        const int4*   SOn = SO0 + pb1 * 128;
        const int cb = ((j + 1) & 7) * 32 + sq * 8;
        const uint32_t Ans = (uint32_t)(SM_A + ns * 8192);

        loadB3(sb, j + 1, ns, tid);
        CP_COMMIT();

        const uint32_t Ab = sb + SM_A + s * 8192 + rowAoff;
        const uint32_t Bb = sb + SM_B + s * 16384 + rowBoff;

        const int4 o = SOn[spx];
        const float4 w = SWn[spx];

        // gather corners 0,1 (fp16, 1 LDG.128 each)
        uint4 r0 = *(const uint4*)(g_xh + o.x + cb);
        uint4 r1 = *(const uint4*)(g_xh + o.y + cb);

        // ks0: A + B np0/1, acc nt0..3
        uint32_t a0[2][4];
        LDSM4(a0[0], Ab + 0 * 1024 + koffA[0]);
        LDSM4(a0[1], Ab + 1 * 1024 + koffA[0]);
        {
            uint32_t b0[4], b1[4];
            LDSM4(b0, Bb + 0 * 1024 + koffB[0]);
            LDSM4(b1, Bb + 1 * 1024 + koffB[0]);
            #pragma unroll
            for (int mt = 0; mt < 2; ++mt) {
                mma_f16(acc[mt][0], a0[mt], b0);
                mma_f16(acc[mt][1], a0[mt], b0 + 2);
                mma_f16(acc[mt][2], a0[mt], b1);
                mma_f16(acc[mt][3], a0[mt], b1 + 2);
            }
        }
        // partial combine with corners 0,1
        float fa[8], fb[8], c[8];
        h8_to_f8(r0, fa); h8_to_f8(r1, fb);
        #pragma unroll
        for (int i = 0; i < 8; ++i) c[i] = w.x * fa[i] + w.y * fb[i];
        // gather corners 2,3
        uint4 r2 = *(const uint4*)(g_xh + o.z + cb);
        uint4 r3 = *(const uint4*)(g_xh + o.w + cb);

        // ks0: B np2/3, acc nt4..7
        {
            uint32_t b0[4], b1[4];
            LDSM4(b0, Bb + 2 * 1024 + koffB[0]);
            LDSM4(b1, Bb + 3 * 1024 + koffB[0]);
            #pragma unroll
            for (int mt = 0; mt < 2; ++mt) {
                mma_f16(acc[mt][4], a0[mt], b0);
                mma_f16(acc[mt][5], a0[mt], b0 + 2);
                mma_f16(acc[mt][6], a0[mt], b1);
                mma_f16(acc[mt][7], a0[mt], b1 + 2);
            }
        }
        // finish combine + STS
        h8_to_f8(r2, fa); h8_to_f8(r3, fb);
        #pragma unroll
        for (int i = 0; i < 8; ++i) c[i] += w.z * fa[i] + w.w * fb[i];
        {
            __half2 h0 = __floats2half2_rn(c[0], c[1]);
            __half2 h1 = __floats2half2_rn(c[2], c[3]);
            __half2 h2 = __floats2half2_rn(c[4], c[5]);
            __half2 h3 = __floats2half2_rn(c[6], c[7]);
            uint4 st;
            st.x = *(uint32_t*)&h0; st.y = *(uint32_t*)&h1;
            st.z = *(uint32_t*)&h2; st.w = *(uint32_t*)&h3;
            *(uint4*)(smem + Ans + stsoff) = st;
        }
        // ks1: full block
        {
            uint32_t a1[2][4];
            LDSM4(a1[0], Ab + 0 * 1024 + koffA[1]);
            LDSM4(a1[1], Ab + 1 * 1024 + koffA[1]);
            #pragma unroll
            for (int np = 0; np < 4; ++np) {
                uint32_t b[4];
                LDSM4(b, Bb + np * 1024 + koffB[1]);
                #pragma unroll
                for (int mt = 0; mt < 2; ++mt) {
                    mma_f16(acc[mt][np * 2 + 0], a1[mt], b);
                    mma_f16(acc[mt][np * 2 + 1], a1[mt], b + 2);
                }
            }
        }

        if ((j + 2) < 72 && ((j + 2) & 7) == 0) {
            const int kp = (j + 2) >> 3, pb = kp & 1;
            compute_params3(kp, m0 + spx, SW0 + pb * 128 + spx, SO0 + pb * 128 + spx);
        }
        CP_WAIT0();
        __syncthreads();
    }

    // ---------------- Final consume: chunk 71 (stage 1) ----------------
    {
        const uint32_t Ab = sb + SM_A + 1 * 8192 + rowAoff;
        const uint32_t Bb = sb + SM_B + 1 * 16384 + rowBoff;
        #pragma unroll
        for (int ks = 0; ks < 2; ++ks) {
            uint32_t a[2][4];
            LDSM4(a[0], Ab + 0 * 1024 + koffA[ks]);
            LDSM4(a[1], Ab + 1 * 1024 + koffA[ks]);
            #pragma unroll
            for (int np = 0; np < 4; ++np) {
                uint32_t b[4];
                LDSM4(b, Bb + np * 1024 + koffB[ks]);
                #pragma unroll
                for (int mt = 0; mt < 2; ++mt) {
                    mma_f16(acc[mt][np * 2 + 0], a[mt], b);
                    mma_f16(acc[mt][np * 2 + 1], a[mt], b + 2);
                }
            }
        }
    }

    // ---------------- Epilogue: bias + store ----------------
    const int g = lane >> 2, cq = lane & 3;
    #pragma unroll
    for (int nt = 0; nt < 8; ++nt) {
        const int fl = wn * 64 + (nt >> 1) * 16 + (nt & 1) * 8 + 2 * cq;
        const float2 bv = *(const float2*)(bias + fl);
        #pragma unroll
        for (int mt = 0; mt < 2; ++mt) {
            const int r0 = m0 + wm * 32 + mt * 16 + g;
            float2 v0, v1;
            v0.x = acc[mt][nt][0] + bv.x;
            v0.y = acc[mt][nt][1] + bv.y;
            v1.x = acc[mt][nt][2] + bv.x;
            v1.y = acc[mt][nt][3] + bv.y;
            *(float2*)(out + (size_t)r0 * 256 + fl) = v0;
            *(float2*)(out + (size_t)(r0 + 8) * 256 + fl) = v1;
        }
    }
}

// ============================ Launch ============================
extern "C" void kernel_launch(void* const* d_in, const int* in_sizes, int n_in,
                              void* d_out, int out_size) {
    (void)in_sizes; (void)n_in; (void)out_size;
    const float* x    = (const float*)d_in[0];
    const float* omw  = (const float*)d_in[1];
    const float* omb  = (const float*)d_in[2];
    const float* W    = (const float*)d_in[3];
    const float* bias = (const float*)d_in[4];
    float* out = (float*)d_out;

    static bool attr_set = false;
    if (!attr_set) {
        cudaFuncSetAttribute(dcn_mma_kernel,
                             cudaFuncAttributeMaxDynamicSharedMemorySize, SM_TOTAL);
        attr_set = true;
    }

    x_to_h<<<NPIX * CC / (256 * 8), 256>>>(x);
    transpose_w<<<dim3(KTOT / 32, FF / 32), 256>>>(W);
    om_prep_w<<<9, 256>>>(omw);
    om_mma_kernel<<<256, 256>>>(omb);
    dcn_mma_kernel<<<256, 512, SM_TOTAL>>>(bias, out);
}

// round 17
// speedup vs baseline: 1.6164x; 1.0113x over previous
#include <cuda_runtime.h>
#include <cuda_fp16.h>
#include <cstdint>
#include <math.h>

// Problem constants (fixed by the dataset)
#define BB 8
#define HH 64
#define WW 64
#define CC 256
#define FF 256
#define NPIX (BB*HH*WW)   // 32768
#define KTOT 2304         // 9*256

__device__ float g_om[NPIX * 27];
__device__ __half g_Wh[FF * KTOT];     // main weights transposed: Wh[f][k]
__device__ __half g_OMWh[32 * KTOT];   // om weights: OMWh[f][tap*256+c], f 27..31 = 0
__device__ __half g_xh[NPIX * CC];     // fp16 copy of input x

// ============================ helpers ============================
__device__ __forceinline__ uint32_t smem_u32(const void* p) {
    uint32_t a;
    asm("{ .reg .u64 t; cvta.to.shared.u64 t, %1; cvt.u32.u64 %0, t; }"
        : "=r"(a) : "l"(p));
    return a;
}
#define CP_ASYNC16(dst, src) \
    asm volatile("cp.async.cg.shared.global [%0], [%1], 16;" :: "r"(dst), "l"(src) : "memory")
#define CP_ASYNC16Z(dst, src, sz) \
    asm volatile("cp.async.cg.shared.global [%0], [%1], 16, %2;" \
                 :: "r"(dst), "l"(src), "r"(sz) : "memory")
#define CP_COMMIT() asm volatile("cp.async.commit_group;" ::: "memory")
#define CP_WAIT0()  asm volatile("cp.async.wait_group 0;" ::: "memory")
#define CP_WAIT2()  asm volatile("cp.async.wait_group 2;" ::: "memory")

#define LDSM4(r, a) \
    asm volatile("ldmatrix.sync.aligned.m8n8.x4.shared.b16 {%0,%1,%2,%3}, [%4];" \
        : "=r"((r)[0]), "=r"((r)[1]), "=r"((r)[2]), "=r"((r)[3]) : "r"(a))

__device__ __forceinline__ void mma_f16(float* c, const uint32_t* a, const uint32_t* b) {
    asm volatile("mma.sync.aligned.m16n8k16.row.col.f32.f16.f16.f32 "
        "{%0,%1,%2,%3}, {%4,%5,%6,%7}, {%8,%9}, {%0,%1,%2,%3};"
        : "+f"(c[0]), "+f"(c[1]), "+f"(c[2]), "+f"(c[3])
        : "r"(a[0]), "r"(a[1]), "r"(a[2]), "r"(a[3]), "r"(b[0]), "r"(b[1]));
}

// Convert 8 packed halves (uint4) to 8 floats.
__device__ __forceinline__ void h8_to_f8(const uint4& r, float* f) {
    const __half2* h = (const __half2*)&r;
    float2 a = __half22float2(h[0]);
    float2 b = __half22float2(h[1]);
    float2 c = __half22float2(h[2]);
    float2 d = __half22float2(h[3]);
    f[0] = a.x; f[1] = a.y; f[2] = b.x; f[3] = b.y;
    f[4] = c.x; f[5] = c.y; f[6] = d.x; f[7] = d.y;
}

// ============================ Kernel 0: fused prep ============================
// blocks [0,4096): x -> fp16 ; [4096,4672): W transpose+fp16 ; [4672,4681): om W
#define PREP_XH 4096
#define PREP_TW (PREP_XH + 576)
#define PREP_TOTAL (PREP_TW + 9)

__global__ __launch_bounds__(256) void prep_all(
    const float* __restrict__ x, const float* __restrict__ W,
    const float* __restrict__ omw)
{
    __shared__ float t[32][33];
    const int bid = blockIdx.x;
    const int tid = threadIdx.x;

    if (bid < PREP_XH) {
        const int i = (bid * 256 + tid) * 8;
        float4 a = *(const float4*)(x + i);
        float4 b = *(const float4*)(x + i + 4);
        __half2 h0 = __floats2half2_rn(a.x, a.y);
        __half2 h1 = __floats2half2_rn(a.z, a.w);
        __half2 h2 = __floats2half2_rn(b.x, b.y);
        __half2 h3 = __floats2half2_rn(b.z, b.w);
        uint4 st;
        st.x = *(uint32_t*)&h0; st.y = *(uint32_t*)&h1;
        st.z = *(uint32_t*)&h2; st.w = *(uint32_t*)&h3;
        *(uint4*)(g_xh + i) = st;
    } else if (bid < PREP_TW) {
        const int bid2 = bid - PREP_XH;
        const int k0 = (bid2 % 72) * 32, f0 = (bid2 / 72) * 32;
        const int tx = tid & 31, ty = tid >> 5;
        #pragma unroll
        for (int r = 0; r < 32; r += 8)
            t[ty + r][tx] = W[(k0 + ty + r) * 256 + f0 + tx];
        __syncthreads();
        #pragma unroll
        for (int r = 0; r < 32; r += 8)
            g_Wh[(f0 + ty + r) * KTOT + k0 + tx] = __float2half_rn(t[tx][ty + r]);
    } else {
        const int k = (bid - PREP_TW) * 256 + tid;
        if (k < KTOT) {
            #pragma unroll
            for (int f = 0; f < 32; ++f) {
                float v = (f < 27) ? omw[k * 27 + f] : 0.f;
                g_OMWh[f * KTOT + k] = __float2half_rn(v);
            }
        }
    }
}

// ============================ Kernel 1: om conv via fp16 mma ==================
// M=128 pixels/CTA (grid 256), N=32 (27 used), K=2304 in 72 chunks of 32.
// 4-stage cp.async group pipeline: chunk j+3 staged at iteration j; wait_group 2.
__global__ __launch_bounds__(256, 1) void om_mma_kernel(const float* __restrict__ omb) {
    __shared__ __align__(16) char smem[4 * 8192 + 4 * 2048];   // A 32KB + B 8KB
    const uint32_t sb = smem_u32(smem);
    const uint32_t B_OFF = 32768;
    const int tid = threadIdx.x;
    const int lane = tid & 31, wid = tid >> 5;
    const int m0 = blockIdx.x * 128;

    float acc[4][4];
    #pragma unroll
    for (int nt = 0; nt < 4; ++nt)
        #pragma unroll
        for (int q = 0; q < 4; ++q) acc[nt][q] = 0.f;

    const int rA = wid * 16 + (lane & 7) + ((lane >> 3) & 1) * 8;
    const int kbitA = lane >> 4;
    const int rB = (lane & 7) + (lane >> 4) * 8;
    const int kbitB = (lane >> 3) & 1;
    uint32_t koffA[2], koffB[2];
    #pragma unroll
    for (int ks = 0; ks < 2; ++ks) {
        koffA[ks] = (uint32_t)(((ks * 2 + kbitA) ^ ((rA >> 1) & 3)) * 16);
        koffB[ks] = (uint32_t)(((ks * 2 + kbitB) ^ ((rB >> 1) & 3)) * 16);
    }
    const uint32_t rowAoff = (uint32_t)(rA * 64);
    const uint32_t rowBoff = (uint32_t)(rB * 64);

    const int px = tid >> 1, half = tid & 1;
    const int m = m0 + px;
    const int y = (m >> 6) & 63, xc = m & 63, b = m >> 12;

    auto stageA = [&](int j, int stage) {
        const int tap = j >> 3;
        const int ky = tap / 3, kx = tap - ky * 3;
        const int sy = y - 1 + ky, sx = xc - 1 + kx;
        const bool valid = ((unsigned)sy < 64u) && ((unsigned)sx < 64u);
        const int csy = min(max(sy, 0), 63), csx = min(max(sx, 0), 63);
        const __half* src = g_xh + (((b << 12) + csy * 64 + csx) << 8)
                            + (j & 7) * 32 + half * 16;
        const int sz = valid ? 16 : 0;
        const int g0 = half * 2, ss = (px >> 1) & 3;
        const uint32_t base = sb + stage * 8192 + px * 64;
        CP_ASYNC16Z(base + ((g0 ^ ss) * 16), src, sz);
        CP_ASYNC16Z(base + (((g0 + 1) ^ ss) * 16), src + 8, sz);
    };
    auto stageB = [&](int j, int stage) {
        if (tid < 128) {
            const int n = tid >> 2, g = tid & 3;
            const uint32_t dst = sb + B_OFF + stage * 2048 + n * 64
                                 + ((g ^ ((n >> 1) & 3)) * 16);
            CP_ASYNC16(dst, g_OMWh + (size_t)n * KTOT + j * 32 + g * 8);
        }
    };

    // Prologue: stage chunks 0,1,2 as three groups
    #pragma unroll
    for (int p = 0; p < 3; ++p) {
        stageB(p, p);
        stageA(p, p);
        CP_COMMIT();
    }

    for (int j = 0; j < 72; ++j) {
        const int s = j & 3;
        CP_WAIT2();            // pending {j,j+1,j+2} -> chunk j complete
        __syncthreads();
        const uint32_t Ab = sb + s * 8192 + rowAoff;
        const uint32_t Bb = sb + B_OFF + s * 2048 + rowBoff;
        #pragma unroll
        for (int ks = 0; ks < 2; ++ks) {
            uint32_t a[4];
            LDSM4(a, Ab + koffA[ks]);
            uint32_t b0[4], b1[4];
            LDSM4(b0, Bb + 0 * 1024 + koffB[ks]);
            LDSM4(b1, Bb + 1 * 1024 + koffB[ks]);
            mma_f16(acc[0], a, b0);
            mma_f16(acc[1], a, b0 + 2);
            mma_f16(acc[2], a, b1);
            mma_f16(acc[3], a, b1 + 2);
        }
        // Stage chunk j+3 into stage (j+3)&3 (consumed at j-1; barrier passed).
        if (j + 3 < 72) {
            stageB(j + 3, (j + 3) & 3);
            stageA(j + 3, (j + 3) & 3);
        }
        CP_COMMIT();           // always commit (empty at tail) to keep count
    }

    const int g = lane >> 2, cq = lane & 3;
    #pragma unroll
    for (int nt = 0; nt < 4; ++nt) {
        #pragma unroll
        for (int q = 0; q < 4; ++q) {
            const int f = nt * 8 + 2 * cq + (q & 1);
            if (f < 27) {
                const int row = m0 + wid * 16 + g + ((q >> 1) * 8);
                float v = acc[nt][q] + omb[f];
                if (f >= 18) v = 2.f / (1.f + expf(-v));
                g_om[row * 27 + f] = v;
            }
        }
    }
}

// ============================ Kernel 2: fused sampling + fp16 mma GEMM ========
// CTA: 512 threads (16 warps), tile M=128 x N=256. Grid 256 m-tiles.
// Warps: 4(m) x 4(n), warp tile 32x64, fp16 m16n8k16, acc[2 mt][8 nt][4] f32.
// 72 K-chunks of 32 fp16; 2 smem stages; fp16 gathers for j+1 pipelined
// through the MMA blocks of chunk j.
#define SM_SW 0              // [2][128] float4 bilinear weights (4KB)
#define SM_SO 4096           // [2][128] int4 corner offsets (4KB)
#define SM_A  8192           // [2][128][64B] fp16 (16KB)
#define SM_B  24576          // [2][256][64B] fp16 (32KB)
#define SM_TOTAL 57344

__device__ __forceinline__ void compute_params3(int kp, int m, float4* sw4, int4* so4) {
    const float* omp = g_om + m * 27;
    const int y = (m >> 6) & 63, xc = m & 63, b = m >> 12;
    const int ky = kp / 3, kx = kp - ky * 3;
    float py = (float)(y - 1 + ky) + omp[2 * kp];
    float px = (float)(xc - 1 + kx) + omp[2 * kp + 1];
    float msk = omp[18 + kp];
    float y0f = floorf(py), x0f = floorf(px);
    float wy1 = py - y0f, wy0 = 1.f - wy1;
    float wx1 = px - x0f, wx0 = 1.f - wx1;
    int iy0 = (int)y0f, ix0 = (int)x0f;
    int iy1 = iy0 + 1, ix1 = ix0 + 1;
    bool vy0 = (unsigned)iy0 < 64u, vy1 = (unsigned)iy1 < 64u;
    bool vx0 = (unsigned)ix0 < 64u, vx1 = (unsigned)ix1 < 64u;
    int cy0 = min(max(iy0, 0), 63), cy1 = min(max(iy1, 0), 63);
    int cx0 = min(max(ix0, 0), 63), cx1 = min(max(ix1, 0), 63);
    int base = b << 12;
    int4 o;
    o.x = (base + cy0 * 64 + cx0) << 8;
    o.y = (base + cy0 * 64 + cx1) << 8;
    o.z = (base + cy1 * 64 + cx0) << 8;
    o.w = (base + cy1 * 64 + cx1) << 8;
    float4 w;
    w.x = (vy0 && vx0) ? wy0 * wx0 * msk : 0.f;
    w.y = (vy0 && vx1) ? wy0 * wx1 * msk : 0.f;
    w.z = (vy1 && vx0) ? wy1 * wx0 * msk : 0.f;
    w.w = (vy1 && vx1) ? wy1 * wx1 * msk : 0.f;
    *so4 = o;
    *sw4 = w;
}

// Stage B chunk j with 512 threads: n = tid>>1, two 16B granules each.
__device__ __forceinline__ void loadB3(uint32_t sb, int j, int stage, int tid) {
    const int n = tid >> 1, g0 = (tid & 1) * 2;
    const int ss = (n >> 1) & 3;
    const uint32_t dbase = sb + SM_B + stage * 16384 + n * 64;
    const __half* src = g_Wh + (size_t)n * KTOT + j * 32;
    CP_ASYNC16(dbase + ((g0 ^ ss) * 16), src + g0 * 8);
    CP_ASYNC16(dbase + (((g0 + 1) ^ ss) * 16), src + (g0 + 1) * 8);
}

__global__ __launch_bounds__(512, 1) void dcn_mma_kernel(
    const float* __restrict__ bias,   // [256]
    float* __restrict__ out)          // [32768,256]
{
    extern __shared__ char smem[];
    const uint32_t sb = smem_u32(smem);
    const int tid = threadIdx.x;
    const int lane = tid & 31, wid = tid >> 5;
    const int wm = wid & 3, wn = wid >> 2;     // 4m x 4n
    const int m0 = blockIdx.x * 128;

    float4* SW0 = (float4*)(smem + SM_SW);
    int4*   SO0 = (int4*)(smem + SM_SO);

    float acc[2][8][4];
    #pragma unroll
    for (int mt = 0; mt < 2; ++mt)
        #pragma unroll
        for (int nt = 0; nt < 8; ++nt)
            #pragma unroll
            for (int q = 0; q < 4; ++q) acc[mt][nt][q] = 0.f;

    // ldmatrix addressing
    const int rA = wm * 32 + (lane & 7) + ((lane >> 3) & 1) * 8;
    const int kbitA = lane >> 4;
    const int rB = wn * 64 + (lane & 7) + (lane >> 4) * 8;
    const int kbitB = (lane >> 3) & 1;
    uint32_t koffA[2], koffB[2];
    #pragma unroll
    for (int ks = 0; ks < 2; ++ks) {
        koffA[ks] = (uint32_t)(((ks * 2 + kbitA) ^ ((rA >> 1) & 3)) * 16);
        koffB[ks] = (uint32_t)(((ks * 2 + kbitB) ^ ((rB >> 1) & 3)) * 16);
    }
    const uint32_t rowAoff = (uint32_t)(rA * 64);
    const uint32_t rowBoff = (uint32_t)(rB * 64);

    // sampling identity: 4 threads per pixel, thread owns 8 channels
    const int spx = tid >> 2, sq = tid & 3;
    const uint32_t stsoff = (uint32_t)(spx * 64 + ((sq ^ ((spx >> 1) & 3)) * 16));

    // ---------------- Prologue ----------------
    compute_params3(0, m0 + spx, SW0 + spx, SO0 + spx);  // 4-way dup, same data
    __syncthreads();
    loadB3(sb, 0, 0, tid);
    CP_COMMIT();
    {
        const int cb = sq * 8;
        const int4 o = SO0[spx];
        const float4 w = SW0[spx];
        uint4 r0 = *(const uint4*)(g_xh + o.x + cb);
        uint4 r1 = *(const uint4*)(g_xh + o.y + cb);
        uint4 r2 = *(const uint4*)(g_xh + o.z + cb);
        uint4 r3 = *(const uint4*)(g_xh + o.w + cb);
        float f0[8], f1[8], f2[8], f3[8], c[8];
        h8_to_f8(r0, f0); h8_to_f8(r1, f1); h8_to_f8(r2, f2); h8_to_f8(r3, f3);
        #pragma unroll
        for (int i = 0; i < 8; ++i)
            c[i] = w.x * f0[i] + w.y * f1[i] + w.z * f2[i] + w.w * f3[i];
        __half2 h0 = __floats2half2_rn(c[0], c[1]);
        __half2 h1 = __floats2half2_rn(c[2], c[3]);
        __half2 h2 = __floats2half2_rn(c[4], c[5]);
        __half2 h3 = __floats2half2_rn(c[6], c[7]);
        uint4 st;
        st.x = *(uint32_t*)&h0; st.y = *(uint32_t*)&h1;
        st.z = *(uint32_t*)&h2; st.w = *(uint32_t*)&h3;
        *(uint4*)(smem + SM_A + stsoff) = st;
    }
    CP_WAIT0();
    __syncthreads();

    // ---------------- Main loop: consume j, produce j+1 ----------------
    for (int j = 0; j < 71; ++j) {
        const int s = j & 1, ns = s ^ 1;
        const int pb1 = ((j + 1) >> 3) & 1;
        const float4* SWn = SW0 + pb1 * 128;
        const int4*   SOn = SO0 + pb1 * 128;
        const int cb = ((j + 1) & 7) * 32 + sq * 8;
        const uint32_t Ans = (uint32_t)(SM_A + ns * 8192);

        loadB3(sb, j + 1, ns, tid);
        CP_COMMIT();

        const uint32_t Ab = sb + SM_A + s * 8192 + rowAoff;
        const uint32_t Bb = sb + SM_B + s * 16384 + rowBoff;

        const int4 o = SOn[spx];
        const float4 w = SWn[spx];

        // gather corners 0,1 (fp16, 1 LDG.128 each)
        uint4 r0 = *(const uint4*)(g_xh + o.x + cb);
        uint4 r1 = *(const uint4*)(g_xh + o.y + cb);

        // ks0: A + B np0/1, acc nt0..3
        uint32_t a0[2][4];
        LDSM4(a0[0], Ab + 0 * 1024 + koffA[0]);
        LDSM4(a0[1], Ab + 1 * 1024 + koffA[0]);
        {
            uint32_t b0[4], b1[4];
            LDSM4(b0, Bb + 0 * 1024 + koffB[0]);
            LDSM4(b1, Bb + 1 * 1024 + koffB[0]);
            #pragma unroll
            for (int mt = 0; mt < 2; ++mt) {
                mma_f16(acc[mt][0], a0[mt], b0);
                mma_f16(acc[mt][1], a0[mt], b0 + 2);
                mma_f16(acc[mt][2], a0[mt], b1);
                mma_f16(acc[mt][3], a0[mt], b1 + 2);
            }
        }
        // partial combine with corners 0,1
        float fa[8], fb[8], c[8];
        h8_to_f8(r0, fa); h8_to_f8(r1, fb);
        #pragma unroll
        for (int i = 0; i < 8; ++i) c[i] = w.x * fa[i] + w.y * fb[i];
        // gather corners 2,3
        uint4 r2 = *(const uint4*)(g_xh + o.z + cb);
        uint4 r3 = *(const uint4*)(g_xh + o.w + cb);

        // ks0: B np2/3, acc nt4..7
        {
            uint32_t b0[4], b1[4];
            LDSM4(b0, Bb + 2 * 1024 + koffB[0]);
            LDSM4(b1, Bb + 3 * 1024 + koffB[0]);
            #pragma unroll
            for (int mt = 0; mt < 2; ++mt) {
                mma_f16(acc[mt][4], a0[mt], b0);
                mma_f16(acc[mt][5], a0[mt], b0 + 2);
                mma_f16(acc[mt][6], a0[mt], b1);
                mma_f16(acc[mt][7], a0[mt], b1 + 2);
            }
        }
        // finish combine + STS
        h8_to_f8(r2, fa); h8_to_f8(r3, fb);
        #pragma unroll
        for (int i = 0; i < 8; ++i) c[i] += w.z * fa[i] + w.w * fb[i];
        {
            __half2 h0 = __floats2half2_rn(c[0], c[1]);
            __half2 h1 = __floats2half2_rn(c[2], c[3]);
            __half2 h2 = __floats2half2_rn(c[4], c[5]);
            __half2 h3 = __floats2half2_rn(c[6], c[7]);
            uint4 st;
            st.x = *(uint32_t*)&h0; st.y = *(uint32_t*)&h1;
            st.z = *(uint32_t*)&h2; st.w = *(uint32_t*)&h3;
            *(uint4*)(smem + Ans + stsoff) = st;
        }
        // ks1: full block
        {
            uint32_t a1[2][4];
            LDSM4(a1[0], Ab + 0 * 1024 + koffA[1]);
            LDSM4(a1[1], Ab + 1 * 1024 + koffA[1]);
            #pragma unroll
            for (int np = 0; np < 4; ++np) {
                uint32_t b[4];
                LDSM4(b, Bb + np * 1024 + koffB[1]);
                #pragma unroll
                for (int mt = 0; mt < 2; ++mt) {
                    mma_f16(acc[mt][np * 2 + 0], a1[mt], b);
                    mma_f16(acc[mt][np * 2 + 1], a1[mt], b + 2);
                }
            }
        }

        if ((j + 2) < 72 && ((j + 2) & 7) == 0) {
            const int kp = (j + 2) >> 3, pb = kp & 1;
            compute_params3(kp, m0 + spx, SW0 + pb * 128 + spx, SO0 + pb * 128 + spx);
        }
        CP_WAIT0();
        __syncthreads();
    }

    // ---------------- Final consume: chunk 71 (stage 1) ----------------
    {
        const uint32_t Ab = sb + SM_A + 1 * 8192 + rowAoff;
        const uint32_t Bb = sb + SM_B + 1 * 16384 + rowBoff;
        #pragma unroll
        for (int ks = 0; ks < 2; ++ks) {
            uint32_t a[2][4];
            LDSM4(a[0], Ab + 0 * 1024 + koffA[ks]);
            LDSM4(a[1], Ab + 1 * 1024 + koffA[ks]);
            #pragma unroll
            for (int np = 0; np < 4; ++np) {
                uint32_t b[4];
                LDSM4(b, Bb + np * 1024 + koffB[ks]);
                #pragma unroll
                for (int mt = 0; mt < 2; ++mt) {
                    mma_f16(acc[mt][np * 2 + 0], a[mt], b);
                    mma_f16(acc[mt][np * 2 + 1], a[mt], b + 2);
                }
            }
        }
    }

    // ---------------- Epilogue: bias + store ----------------
    const int g = lane >> 2, cq = lane & 3;
    #pragma unroll
    for (int nt = 0; nt < 8; ++nt) {
        const int fl = wn * 64 + (nt >> 1) * 16 + (nt & 1) * 8 + 2 * cq;
        const float2 bv = *(const float2*)(bias + fl);
        #pragma unroll
        for (int mt = 0; mt < 2; ++mt) {
            const int r0 = m0 + wm * 32 + mt * 16 + g;
            float2 v0, v1;
            v0.x = acc[mt][nt][0] + bv.x;
            v0.y = acc[mt][nt][1] + bv.y;
            v1.x = acc[mt][nt][2] + bv.x;
            v1.y = acc[mt][nt][3] + bv.y;
            *(float2*)(out + (size_t)r0 * 256 + fl) = v0;
            *(float2*)(out + (size_t)(r0 + 8) * 256 + fl) = v1;
        }
    }
}

// ============================ Launch ============================
extern "C" void kernel_launch(void* const* d_in, const int* in_sizes, int n_in,
                              void* d_out, int out_size) {
    (void)in_sizes; (void)n_in; (void)out_size;
    const float* x    = (const float*)d_in[0];
    const float* omw  = (const float*)d_in[1];
    const float* omb  = (const float*)d_in[2];
    const float* W    = (const float*)d_in[3];
    const float* bias = (const float*)d_in[4];
    float* out = (float*)d_out;

    static bool attr_set = false;
    if (!attr_set) {
        cudaFuncSetAttribute(dcn_mma_kernel,
                             cudaFuncAttributeMaxDynamicSharedMemorySize, SM_TOTAL);
        attr_set = true;
    }

    prep_all<<<PREP_TOTAL, 256>>>(x, W, omw);
    om_mma_kernel<<<256, 256>>>(omb);
    dcn_mma_kernel<<<256, 512, SM_TOTAL>>>(bias, out);
}